// round 13
// baseline (speedup 1.0000x reference)
#include <cuda_runtime.h>
#include <cstdint>

#define N_NODES 50000
#define N_EDGES 800000
#define IN_F 128
#define HID 128
#define OUT_F 64

typedef unsigned long long u64;

// ---------------- scratch (device globals: no allocation allowed) ----------
__device__ float g_xw0[(size_t)N_NODES * HID];   // x @ w0
__device__ float g_h[(size_t)N_NODES * HID];     // relu(spmm(x@w0))
__device__ float g_hw1[(size_t)N_NODES * OUT_F]; // h @ w1
__device__ int   g_rowptr[N_NODES + 1];
__device__ int   g_is64;                         // 1 if edge indices are int64

// ---------------- packed fp32x2 helpers (Blackwell FFMA2) ------------------
__device__ __forceinline__ u64 pack2(float lo, float hi) {
    u64 r;
    asm("mov.b64 %0, {%1, %2};" : "=l"(r) : "f"(lo), "f"(hi));
    return r;
}
__device__ __forceinline__ void unpack2(u64 v, float& lo, float& hi) {
    asm("mov.b64 {%0, %1}, %2;" : "=f"(lo), "=f"(hi) : "l"(v));
}
__device__ __forceinline__ void ffma2(u64& d, u64 a, u64 b) {
    asm("fma.rn.f32x2 %0, %1, %2, %0;" : "+l"(d) : "l"(a), "l"(b));
}

// ---------------- dtype detection (parallel) --------------------------------
__global__ void detect_kernel(const unsigned int* __restrict__ ec_words) {
    __shared__ unsigned int red[8];
    unsigned int acc = 0;
    for (int i = threadIdx.x; i < 4096; i += 256) acc |= ec_words[2 * i + 1];
#pragma unroll
    for (int o = 16; o; o >>= 1) acc |= __shfl_xor_sync(0xffffffffu, acc, o);
    if ((threadIdx.x & 31) == 0) red[threadIdx.x >> 5] = acc;
    __syncthreads();
    if (threadIdx.x == 0) {
        unsigned int a = 0;
#pragma unroll
        for (int i = 0; i < 8; i++) a |= red[i];
        g_is64 = (a == 0) ? 1 : 0;
    }
}

__device__ __forceinline__ long long load_idx(const void* p, int e, int is64) {
    if (is64) return ((const long long*)p)[e];
    return (long long)((const int*)p)[e];
}

// ---------------- CSR row_ptr via binary search (edge_row is sorted) -------
__global__ void rowptr_kernel(const void* __restrict__ edge_row) {
    int i = blockIdx.x * blockDim.x + threadIdx.x;
    if (i > N_NODES) return;
    const int is64 = g_is64;
    int lo = 0, hi = N_EDGES;
    while (lo < hi) {
        int mid = (lo + hi) >> 1;
        if (load_idx(edge_row, mid, is64) < (long long)i) lo = mid + 1;
        else hi = mid;
    }
    g_rowptr[i] = lo;
}

// ---------------- GEMM1: g_xw0 = x[50000,128] @ w0[128,128] ----------------
// CTA: 128 rows x 128 cols, 256 threads, 8x8 micro-tile, packed f32x2 pairs.
#define G1_KT 32
__global__ __launch_bounds__(256, 2) void gemm1_kernel(
        const float* __restrict__ x, const float* __restrict__ w0) {
    __shared__ float As[G1_KT][128];   // 16 KB
    __shared__ float Bs[G1_KT][128];   // 16 KB
    const int tid = threadIdx.x;
    const int tx = tid & 15;          // 16 col-groups of 8
    const int ty = tid >> 4;          // 16 row-groups of 8
    const int row0 = blockIdx.x * 128;

    u64 acc2[8][4];                    // 8 rows x 4 col-pairs
#pragma unroll
    for (int i = 0; i < 8; i++)
#pragma unroll
        for (int j = 0; j < 4; j++) acc2[i][j] = 0ull;

    for (int kt = 0; kt < IN_F; kt += G1_KT) {
#pragma unroll
        for (int s = tid; s < 1024; s += 256) {
            int r = s >> 3, kq = s & 7;
            int row = row0 + r;
            float4 v = make_float4(0.f, 0.f, 0.f, 0.f);
            if (row < N_NODES)
                v = *reinterpret_cast<const float4*>(x + (size_t)row * IN_F + kt + kq * 4);
            As[kq * 4 + 0][r] = v.x;
            As[kq * 4 + 1][r] = v.y;
            As[kq * 4 + 2][r] = v.z;
            As[kq * 4 + 3][r] = v.w;
        }
#pragma unroll
        for (int s = tid; s < 1024; s += 256) {
            int k = s >> 5, cq = s & 31;
            *reinterpret_cast<float4*>(&Bs[k][cq * 4]) =
                *reinterpret_cast<const float4*>(w0 + (size_t)(kt + k) * HID + cq * 4);
        }
        __syncthreads();
#pragma unroll
        for (int k = 0; k < G1_KT; k++) {
            float4 a0 = *reinterpret_cast<const float4*>(&As[k][ty * 8]);
            float4 a1 = *reinterpret_cast<const float4*>(&As[k][ty * 8 + 4]);
            float4 b0 = *reinterpret_cast<const float4*>(&Bs[k][tx * 8]);
            float4 b1 = *reinterpret_cast<const float4*>(&Bs[k][tx * 8 + 4]);
            u64 bp[4] = {pack2(b0.x, b0.y), pack2(b0.z, b0.w),
                         pack2(b1.x, b1.y), pack2(b1.z, b1.w)};
            float av[8] = {a0.x, a0.y, a0.z, a0.w, a1.x, a1.y, a1.z, a1.w};
#pragma unroll
            for (int i = 0; i < 8; i++) {
                u64 ap = pack2(av[i], av[i]);
#pragma unroll
                for (int j = 0; j < 4; j++) ffma2(acc2[i][j], ap, bp[j]);
            }
        }
        __syncthreads();
    }
#pragma unroll
    for (int i = 0; i < 8; i++) {
        int row = row0 + ty * 8 + i;
        if (row < N_NODES) {
            float4 o0, o1;
            unpack2(acc2[i][0], o0.x, o0.y);
            unpack2(acc2[i][1], o0.z, o0.w);
            unpack2(acc2[i][2], o1.x, o1.y);
            unpack2(acc2[i][3], o1.z, o1.w);
            *reinterpret_cast<float4*>(g_xw0 + (size_t)row * HID + tx * 8) = o0;
            *reinterpret_cast<float4*>(g_xw0 + (size_t)row * HID + tx * 8 + 4) = o1;
        }
    }
}

// ---------------- SpMM1 + ReLU: one warp per node, float4 per lane ---------
__global__ void spmm1_kernel(const void* __restrict__ edge_col,
                             const float* __restrict__ edge_weight) {
    int gwarp = (blockIdx.x * blockDim.x + threadIdx.x) >> 5;
    int lane = threadIdx.x & 31;
    if (gwarp >= N_NODES) return;
    const int is64 = g_is64;
    int beg = g_rowptr[gwarp];
    int end = g_rowptr[gwarp + 1];
    const float4* feat = reinterpret_cast<const float4*>(g_xw0);
    float4 acc = make_float4(0.f, 0.f, 0.f, 0.f);
    for (int e = beg; e < end; e++) {
        float w = __ldg(edge_weight + e);
        int c = (int)load_idx(edge_col, e, is64);
        float4 v = feat[(size_t)c * 32 + lane];
        acc.x += w * v.x; acc.y += w * v.y;
        acc.z += w * v.z; acc.w += w * v.w;
    }
    float4 r;
    r.x = fmaxf(acc.x, 0.f); r.y = fmaxf(acc.y, 0.f);
    r.z = fmaxf(acc.z, 0.f); r.w = fmaxf(acc.w, 0.f);
    reinterpret_cast<float4*>(g_h)[(size_t)gwarp * 32 + lane] = r;
}

// ---------------- GEMM2: g_hw1 = g_h[50000,128] @ w1[128,64] ---------------
// CTA: 128 rows x 64 cols, 256 threads, 4x8 micro-tile, packed f32x2 pairs.
#define G2_KT 32
__global__ __launch_bounds__(256, 2) void gemm2_kernel(const float* __restrict__ w1) {
    __shared__ float As[G2_KT][128];   // 16 KB
    __shared__ float Bs[G2_KT][64];    //  8 KB
    const int tid = threadIdx.x;
    const int tx = tid & 7;           // 8 col-groups of 8
    const int ty = tid >> 3;          // 32 row-groups of 4
    const int row0 = blockIdx.x * 128;

    u64 acc2[4][4];                    // 4 rows x 4 col-pairs
#pragma unroll
    for (int i = 0; i < 4; i++)
#pragma unroll
        for (int j = 0; j < 4; j++) acc2[i][j] = 0ull;

    for (int kt = 0; kt < HID; kt += G2_KT) {
#pragma unroll
        for (int s = tid; s < 1024; s += 256) {
            int r = s >> 3, kq = s & 7;
            int row = row0 + r;
            float4 v = make_float4(0.f, 0.f, 0.f, 0.f);
            if (row < N_NODES)
                v = *reinterpret_cast<const float4*>(g_h + (size_t)row * HID + kt + kq * 4);
            As[kq * 4 + 0][r] = v.x;
            As[kq * 4 + 1][r] = v.y;
            As[kq * 4 + 2][r] = v.z;
            As[kq * 4 + 3][r] = v.w;
        }
#pragma unroll
        for (int s = tid; s < 512; s += 256) {
            int k = s >> 4, cq = s & 15;
            *reinterpret_cast<float4*>(&Bs[k][cq * 4]) =
                *reinterpret_cast<const float4*>(w1 + (size_t)(kt + k) * OUT_F + cq * 4);
        }
        __syncthreads();
#pragma unroll
        for (int k = 0; k < G2_KT; k++) {
            float4 a0 = *reinterpret_cast<const float4*>(&As[k][ty * 4]);
            float4 b0 = *reinterpret_cast<const float4*>(&Bs[k][tx * 8]);
            float4 b1 = *reinterpret_cast<const float4*>(&Bs[k][tx * 8 + 4]);
            u64 bp[4] = {pack2(b0.x, b0.y), pack2(b0.z, b0.w),
                         pack2(b1.x, b1.y), pack2(b1.z, b1.w)};
            float av[4] = {a0.x, a0.y, a0.z, a0.w};
#pragma unroll
            for (int i = 0; i < 4; i++) {
                u64 ap = pack2(av[i], av[i]);
#pragma unroll
                for (int j = 0; j < 4; j++) ffma2(acc2[i][j], ap, bp[j]);
            }
        }
        __syncthreads();
    }
#pragma unroll
    for (int i = 0; i < 4; i++) {
        int row = row0 + ty * 4 + i;
        if (row < N_NODES) {
            float4 o0, o1;
            unpack2(acc2[i][0], o0.x, o0.y);
            unpack2(acc2[i][1], o0.z, o0.w);
            unpack2(acc2[i][2], o1.x, o1.y);
            unpack2(acc2[i][3], o1.z, o1.w);
            *reinterpret_cast<float4*>(g_hw1 + (size_t)row * OUT_F + tx * 8) = o0;
            *reinterpret_cast<float4*>(g_hw1 + (size_t)row * OUT_F + tx * 8 + 4) = o1;
        }
    }
}

// ---------------- SpMM2: one warp per node, float2 per lane ----------------
__global__ void spmm2_kernel(const void* __restrict__ edge_col,
                             const float* __restrict__ edge_weight,
                             float* __restrict__ out) {
    int gwarp = (blockIdx.x * blockDim.x + threadIdx.x) >> 5;
    int lane = threadIdx.x & 31;
    if (gwarp >= N_NODES) return;
    const int is64 = g_is64;
    int beg = g_rowptr[gwarp];
    int end = g_rowptr[gwarp + 1];
    const float2* feat = reinterpret_cast<const float2*>(g_hw1);
    float2 acc = make_float2(0.f, 0.f);
    for (int e = beg; e < end; e++) {
        float w = __ldg(edge_weight + e);
        int c = (int)load_idx(edge_col, e, is64);
        float2 v = feat[(size_t)c * 32 + lane];
        acc.x += w * v.x; acc.y += w * v.y;
    }
    reinterpret_cast<float2*>(out)[(size_t)gwarp * 32 + lane] = acc;
}

// ---------------- launch ---------------------------------------------------
extern "C" void kernel_launch(void* const* d_in, const int* in_sizes, int n_in,
                              void* d_out, int out_size) {
    const float* x  = (const float*)d_in[0];
    const void*  er = d_in[1];
    const void*  ec = d_in[2];
    const float* ew = (const float*)d_in[3];
    const float* w0 = (const float*)d_in[4];
    const float* w1 = (const float*)d_in[5];
    float* out = (float*)d_out;

    detect_kernel<<<1, 256>>>((const unsigned int*)ec);
    rowptr_kernel<<<(N_NODES + 1 + 255) / 256, 256>>>(er);
    gemm1_kernel<<<(N_NODES + 127) / 128, 256>>>(x, w0);
    spmm1_kernel<<<(N_NODES * 32 + 255) / 256, 256>>>(ec, ew);
    gemm2_kernel<<<(N_NODES + 127) / 128, 256>>>(w1);
    spmm2_kernel<<<(N_NODES * 32 + 255) / 256, 256>>>(ec, ew, out);
}

// round 14
// speedup vs baseline: 1.1067x; 1.1067x over previous
#include <cuda_runtime.h>
#include <cuda_fp16.h>
#include <cstdint>

#define N_NODES 50000
#define N_EDGES 800000
#define IN_F 128
#define HID 128
#define OUT_F 64

typedef unsigned long long u64;

// ---------------- scratch (device globals: no allocation allowed) ----------
__device__ __half g_xw0h[(size_t)N_NODES * HID];  // x @ w0  (fp16, gather target)
__device__ float  g_h[(size_t)N_NODES * HID];     // relu(spmm(xw0)) (fp32)
__device__ __half g_hw1h[(size_t)N_NODES * OUT_F];// h @ w1  (fp16, gather target)
__device__ int    g_rowptr[N_NODES + 1];
__device__ int    g_is64;                         // 1 if edge indices are int64

// ---------------- packed fp32x2 helpers ------------------------------------
__device__ __forceinline__ u64 pack2(float lo, float hi) {
    u64 r;
    asm("mov.b64 %0, {%1, %2};" : "=l"(r) : "f"(lo), "f"(hi));
    return r;
}
__device__ __forceinline__ void unpack2(u64 v, float& lo, float& hi) {
    asm("mov.b64 {%0, %1}, %2;" : "=f"(lo), "=f"(hi) : "l"(v));
}
__device__ __forceinline__ void ffma2(u64& d, u64 a, u64 b) {
    asm("fma.rn.f32x2 %0, %1, %2, %0;" : "+l"(d) : "l"(a), "l"(b));
}

// ---------------- dtype detection (parallel) --------------------------------
__global__ void detect_kernel(const unsigned int* __restrict__ ec_words) {
    __shared__ unsigned int red[8];
    unsigned int acc = 0;
    for (int i = threadIdx.x; i < 4096; i += 256) acc |= ec_words[2 * i + 1];
#pragma unroll
    for (int o = 16; o; o >>= 1) acc |= __shfl_xor_sync(0xffffffffu, acc, o);
    if ((threadIdx.x & 31) == 0) red[threadIdx.x >> 5] = acc;
    __syncthreads();
    if (threadIdx.x == 0) {
        unsigned int a = 0;
#pragma unroll
        for (int i = 0; i < 8; i++) a |= red[i];
        g_is64 = (a == 0) ? 1 : 0;
    }
}

__device__ __forceinline__ long long load_idx(const void* p, int e, int is64) {
    if (is64) return ((const long long*)p)[e];
    return (long long)((const int*)p)[e];
}

// ---------------- CSR row_ptr via binary search (edge_row is sorted) -------
__global__ void rowptr_kernel(const void* __restrict__ edge_row) {
    int i = blockIdx.x * blockDim.x + threadIdx.x;
    if (i > N_NODES) return;
    const int is64 = g_is64;
    int lo = 0, hi = N_EDGES;
    while (lo < hi) {
        int mid = (lo + hi) >> 1;
        if (load_idx(edge_row, mid, is64) < (long long)i) lo = mid + 1;
        else hi = mid;
    }
    g_rowptr[i] = lo;
}

// ---------------- GEMM1: g_xw0h = fp16(x[50000,128] @ w0[128,128]) ---------
#define G1_KT 32
__global__ __launch_bounds__(256, 2) void gemm1_kernel(
        const float* __restrict__ x, const float* __restrict__ w0) {
    __shared__ float As[G1_KT][128];
    __shared__ float Bs[G1_KT][128];
    const int tid = threadIdx.x;
    const int tx = tid & 15;
    const int ty = tid >> 4;
    const int row0 = blockIdx.x * 128;

    u64 acc2[8][4];
#pragma unroll
    for (int i = 0; i < 8; i++)
#pragma unroll
        for (int j = 0; j < 4; j++) acc2[i][j] = 0ull;

    for (int kt = 0; kt < IN_F; kt += G1_KT) {
#pragma unroll
        for (int s = tid; s < 1024; s += 256) {
            int r = s >> 3, kq = s & 7;
            int row = row0 + r;
            float4 v = make_float4(0.f, 0.f, 0.f, 0.f);
            if (row < N_NODES)
                v = *reinterpret_cast<const float4*>(x + (size_t)row * IN_F + kt + kq * 4);
            As[kq * 4 + 0][r] = v.x;
            As[kq * 4 + 1][r] = v.y;
            As[kq * 4 + 2][r] = v.z;
            As[kq * 4 + 3][r] = v.w;
        }
#pragma unroll
        for (int s = tid; s < 1024; s += 256) {
            int k = s >> 5, cq = s & 31;
            *reinterpret_cast<float4*>(&Bs[k][cq * 4]) =
                *reinterpret_cast<const float4*>(w0 + (size_t)(kt + k) * HID + cq * 4);
        }
        __syncthreads();
#pragma unroll
        for (int k = 0; k < G1_KT; k++) {
            float4 a0 = *reinterpret_cast<const float4*>(&As[k][ty * 8]);
            float4 a1 = *reinterpret_cast<const float4*>(&As[k][ty * 8 + 4]);
            float4 b0 = *reinterpret_cast<const float4*>(&Bs[k][tx * 8]);
            float4 b1 = *reinterpret_cast<const float4*>(&Bs[k][tx * 8 + 4]);
            u64 bp[4] = {pack2(b0.x, b0.y), pack2(b0.z, b0.w),
                         pack2(b1.x, b1.y), pack2(b1.z, b1.w)};
            float av[8] = {a0.x, a0.y, a0.z, a0.w, a1.x, a1.y, a1.z, a1.w};
#pragma unroll
            for (int i = 0; i < 8; i++) {
                u64 ap = pack2(av[i], av[i]);
#pragma unroll
                for (int j = 0; j < 4; j++) ffma2(acc2[i][j], ap, bp[j]);
            }
        }
        __syncthreads();
    }
#pragma unroll
    for (int i = 0; i < 8; i++) {
        int row = row0 + ty * 8 + i;
        if (row < N_NODES) {
            float f0, f1, f2, f3, f4, f5, f6, f7;
            unpack2(acc2[i][0], f0, f1);
            unpack2(acc2[i][1], f2, f3);
            unpack2(acc2[i][2], f4, f5);
            unpack2(acc2[i][3], f6, f7);
            __half2 h0 = __floats2half2_rn(f0, f1);
            __half2 h1 = __floats2half2_rn(f2, f3);
            __half2 h2 = __floats2half2_rn(f4, f5);
            __half2 h3 = __floats2half2_rn(f6, f7);
            uint4 o;
            o.x = *reinterpret_cast<uint32_t*>(&h0);
            o.y = *reinterpret_cast<uint32_t*>(&h1);
            o.z = *reinterpret_cast<uint32_t*>(&h2);
            o.w = *reinterpret_cast<uint32_t*>(&h3);
            *reinterpret_cast<uint4*>(g_xw0h + (size_t)row * HID + tx * 8) = o;
        }
    }
}

// ---------------- SpMM1 + ReLU: one warp per node, 4 fp16 feats per lane ---
__global__ void spmm1_kernel(const void* __restrict__ edge_col,
                             const float* __restrict__ edge_weight) {
    int gwarp = (blockIdx.x * blockDim.x + threadIdx.x) >> 5;
    int lane = threadIdx.x & 31;
    if (gwarp >= N_NODES) return;
    const int is64 = g_is64;
    int beg = g_rowptr[gwarp];
    int end = g_rowptr[gwarp + 1];
    const uint2* feat = reinterpret_cast<const uint2*>(g_xw0h);  // 32 uint2/row
    float4 acc = make_float4(0.f, 0.f, 0.f, 0.f);
    for (int e = beg; e < end; e++) {
        float w = __ldg(edge_weight + e);
        int c = (int)load_idx(edge_col, e, is64);
        uint2 v = feat[(size_t)c * 32 + lane];
        float2 f0 = __half22float2(*reinterpret_cast<__half2*>(&v.x));
        float2 f1 = __half22float2(*reinterpret_cast<__half2*>(&v.y));
        acc.x += w * f0.x; acc.y += w * f0.y;
        acc.z += w * f1.x; acc.w += w * f1.y;
    }
    float4 r;
    r.x = fmaxf(acc.x, 0.f); r.y = fmaxf(acc.y, 0.f);
    r.z = fmaxf(acc.z, 0.f); r.w = fmaxf(acc.w, 0.f);
    reinterpret_cast<float4*>(g_h)[(size_t)gwarp * 32 + lane] = r;
}

// ---------------- GEMM2: g_hw1h = fp16(g_h[50000,128] @ w1[128,64]) --------
#define G2_KT 32
__global__ __launch_bounds__(256, 2) void gemm2_kernel(const float* __restrict__ w1) {
    __shared__ float As[G2_KT][128];
    __shared__ float Bs[G2_KT][64];
    const int tid = threadIdx.x;
    const int tx = tid & 7;
    const int ty = tid >> 3;
    const int row0 = blockIdx.x * 128;

    u64 acc2[4][4];
#pragma unroll
    for (int i = 0; i < 4; i++)
#pragma unroll
        for (int j = 0; j < 4; j++) acc2[i][j] = 0ull;

    for (int kt = 0; kt < HID; kt += G2_KT) {
#pragma unroll
        for (int s = tid; s < 1024; s += 256) {
            int r = s >> 3, kq = s & 7;
            int row = row0 + r;
            float4 v = make_float4(0.f, 0.f, 0.f, 0.f);
            if (row < N_NODES)
                v = *reinterpret_cast<const float4*>(g_h + (size_t)row * HID + kt + kq * 4);
            As[kq * 4 + 0][r] = v.x;
            As[kq * 4 + 1][r] = v.y;
            As[kq * 4 + 2][r] = v.z;
            As[kq * 4 + 3][r] = v.w;
        }
#pragma unroll
        for (int s = tid; s < 512; s += 256) {
            int k = s >> 4, cq = s & 15;
            *reinterpret_cast<float4*>(&Bs[k][cq * 4]) =
                *reinterpret_cast<const float4*>(w1 + (size_t)(kt + k) * OUT_F + cq * 4);
        }
        __syncthreads();
#pragma unroll
        for (int k = 0; k < G2_KT; k++) {
            float4 a0 = *reinterpret_cast<const float4*>(&As[k][ty * 4]);
            float4 b0 = *reinterpret_cast<const float4*>(&Bs[k][tx * 8]);
            float4 b1 = *reinterpret_cast<const float4*>(&Bs[k][tx * 8 + 4]);
            u64 bp[4] = {pack2(b0.x, b0.y), pack2(b0.z, b0.w),
                         pack2(b1.x, b1.y), pack2(b1.z, b1.w)};
            float av[4] = {a0.x, a0.y, a0.z, a0.w};
#pragma unroll
            for (int i = 0; i < 4; i++) {
                u64 ap = pack2(av[i], av[i]);
#pragma unroll
                for (int j = 0; j < 4; j++) ffma2(acc2[i][j], ap, bp[j]);
            }
        }
        __syncthreads();
    }
#pragma unroll
    for (int i = 0; i < 4; i++) {
        int row = row0 + ty * 4 + i;
        if (row < N_NODES) {
            float f0, f1, f2, f3, f4, f5, f6, f7;
            unpack2(acc2[i][0], f0, f1);
            unpack2(acc2[i][1], f2, f3);
            unpack2(acc2[i][2], f4, f5);
            unpack2(acc2[i][3], f6, f7);
            __half2 h0 = __floats2half2_rn(f0, f1);
            __half2 h1 = __floats2half2_rn(f2, f3);
            __half2 h2 = __floats2half2_rn(f4, f5);
            __half2 h3 = __floats2half2_rn(f6, f7);
            uint4 o;
            o.x = *reinterpret_cast<uint32_t*>(&h0);
            o.y = *reinterpret_cast<uint32_t*>(&h1);
            o.z = *reinterpret_cast<uint32_t*>(&h2);
            o.w = *reinterpret_cast<uint32_t*>(&h3);
            *reinterpret_cast<uint4*>(g_hw1h + (size_t)row * OUT_F + tx * 8) = o;
        }
    }
}

// ---------------- SpMM2: one warp per node, 2 fp16 feats per lane ----------
__global__ void spmm2_kernel(const void* __restrict__ edge_col,
                             const float* __restrict__ edge_weight,
                             float* __restrict__ out) {
    int gwarp = (blockIdx.x * blockDim.x + threadIdx.x) >> 5;
    int lane = threadIdx.x & 31;
    if (gwarp >= N_NODES) return;
    const int is64 = g_is64;
    int beg = g_rowptr[gwarp];
    int end = g_rowptr[gwarp + 1];
    const uint32_t* feat = reinterpret_cast<const uint32_t*>(g_hw1h);  // 32/row
    float2 acc = make_float2(0.f, 0.f);
    for (int e = beg; e < end; e++) {
        float w = __ldg(edge_weight + e);
        int c = (int)load_idx(edge_col, e, is64);
        uint32_t v = feat[(size_t)c * 32 + lane];
        float2 f = __half22float2(*reinterpret_cast<__half2*>(&v));
        acc.x += w * f.x; acc.y += w * f.y;
    }
    reinterpret_cast<float2*>(out)[(size_t)gwarp * 32 + lane] = acc;
}

// ---------------- launch ---------------------------------------------------
extern "C" void kernel_launch(void* const* d_in, const int* in_sizes, int n_in,
                              void* d_out, int out_size) {
    const float* x  = (const float*)d_in[0];
    const void*  er = d_in[1];
    const void*  ec = d_in[2];
    const float* ew = (const float*)d_in[3];
    const float* w0 = (const float*)d_in[4];
    const float* w1 = (const float*)d_in[5];
    float* out = (float*)d_out;

    detect_kernel<<<1, 256>>>((const unsigned int*)ec);
    rowptr_kernel<<<(N_NODES + 1 + 255) / 256, 256>>>(er);
    gemm1_kernel<<<(N_NODES + 127) / 128, 256>>>(x, w0);
    spmm1_kernel<<<(N_NODES * 32 + 255) / 256, 256>>>(ec, ew);
    gemm2_kernel<<<(N_NODES + 127) / 128, 256>>>(w1);
    spmm2_kernel<<<(N_NODES * 32 + 255) / 256, 256>>>(ec, ew, out);
}